// round 2
// baseline (speedup 1.0000x reference)
#include <cuda_runtime.h>

// rosa_emb_layer: B=8, T=2048, V=50257, C=768
// inputs: d_in[0] = idx (B,T) int32, d_in[1] = emb (V,C) float32
// output: (B,T,C) float32
//
// L[i,j] = longest common suffix of x[..i], x[..j] (j < i). Reference argmax of
// L + j*1e-5 == integer max of (L<<11)|j (L<=2048, tie-break larger j).
// Random tokens => matches are rare (~i/50257 per row); brute-force equality
// scan from smem, extend backward only on hit. One warp per (b,i), fused
// embedding gather / zero-fill epilogue.
//
// R1 change vs R0: 32-warp CTAs (4x fewer smem fills + barriers), strided
// warp->row assignment i = c + 64*w so every CTA has equal total compare work,
// 2x-unrolled compare loop (two int4 in flight per lane).

#define TT 2048
#define BB 8
#define CC 768
#define WPB 32                    // warps per CTA
#define CPB (TT / WPB)            // CTAs per batch = 64

__global__ __launch_bounds__(WPB * 32, 2)
void rosa_emb_kernel(const int* __restrict__ idx,
                     const float* __restrict__ emb,
                     float* __restrict__ out) {
    __shared__ int xs[TT];

    const int b    = blockIdx.x >> 6;       // / CPB
    const int c    = blockIdx.x & (CPB - 1);
    const int tid  = threadIdx.x;
    const int w    = tid >> 5;
    const int lane = tid & 31;

    // Cooperatively load this batch's token row (8 KB) into shared memory.
    const int4* g  = (const int4*)(idx + (size_t)b * TT);
    int4*       s4 = (int4*)xs;
    if (tid < TT / 4) s4[tid] = g[tid];
    __syncthreads();

    // Strided row assignment: balances compare work across CTAs.
    const int i  = c + CPB * w;             // in [0, 2048)
    const int xi = xs[i];

    // best = (L << 11) | j   (L in [1,2048], j in [0,2047]); 0 == no match.
    int best = 0;

    // Lanes cover j in [0, i): 8 consecutive j per lane per trip (2x int4).
    for (int j0 = lane * 8; j0 < i; j0 += 256) {
        const int q  = j0 >> 2;
        const int4 v0 = s4[q];
        const int4 v1 = s4[q + 1];
        unsigned m = 0;
        m |= (v0.x == xi)                 ? 0x01u : 0u;   // j0 < i guaranteed
        m |= ((v0.y == xi) & (j0+1 < i))  ? 0x02u : 0u;
        m |= ((v0.z == xi) & (j0+2 < i))  ? 0x04u : 0u;
        m |= ((v0.w == xi) & (j0+3 < i))  ? 0x08u : 0u;
        m |= ((v1.x == xi) & (j0+4 < i))  ? 0x10u : 0u;
        m |= ((v1.y == xi) & (j0+5 < i))  ? 0x20u : 0u;
        m |= ((v1.z == xi) & (j0+6 < i))  ? 0x40u : 0u;
        m |= ((v1.w == xi) & (j0+7 < i))  ? 0x80u : 0u;
        while (m) {                                        // rare path
            const int cbit = __ffs(m) - 1;
            m &= m - 1;
            const int j = j0 + cbit;
            int L = 1, t = 1;
            while (t <= j && xs[i - t] == xs[j - t]) { ++L; ++t; }
            const int packed = (L << 11) | j;
            if (packed > best) best = packed;
        }
    }

    // Warp max-reduce the packed (L, j) score.
    #pragma unroll
    for (int o = 16; o; o >>= 1)
        best = max(best, __shfl_xor_sync(0xffffffffu, best, o));

    // Fused epilogue: this warp writes its (b,i) output row of 768 floats.
    float4* orow = (float4*)(out + ((size_t)b * TT + i) * CC);
    if (best < (1 << 11)) {
        const float4 z = make_float4(0.f, 0.f, 0.f, 0.f);
        #pragma unroll
        for (int k = 0; k < CC / 4 / 32; k++) orow[lane + 32 * k] = z;
    } else {
        const int bj = best & 2047;
        int pidx = bj + 1; if (pidx > TT - 1) pidx = TT - 1;
        const int tok = xs[pidx];
        const float4* erow = (const float4*)(emb + (size_t)tok * CC);
        #pragma unroll
        for (int k = 0; k < CC / 4 / 32; k++) orow[lane + 32 * k] = erow[lane + 32 * k];
    }
}

extern "C" void kernel_launch(void* const* d_in, const int* in_sizes, int n_in,
                              void* d_out, int out_size) {
    const int*   idx = (const int*)d_in[0];
    const float* emb = (const float*)d_in[1];
    float*       out = (float*)d_out;

    rosa_emb_kernel<<<BB * CPB, WPB * 32>>>(idx, emb, out);
}